// round 12
// baseline (speedup 1.0000x reference)
#include <cuda_runtime.h>
#include <cuda_bf16.h>

#define NX 192
#define NY 192
#define NZ 192
#define NXY (NX * NY)

#define VEC 2                    // float2 per thread in x
#define SEGW (32 * VEC)          // 64 x per warp
#define WYD 4                    // 4 warps/CTA, 1 y-row each
#define NTHREADS 128
#define ZCHUNK 32                // multiple of 4 (4-step unroll, 2-phase slots)
#define GXB (NX / SEGW)          // 3
#define GYB (NY / WYD)           // 48
#define GZB (NZ / ZCHUNK)        // 6
#define NBLOCKS (GXB * GYB * GZB) // 864 (single wave at 6 CTAs/SM)

#define FULLMASK 0xFFFFFFFFu

typedef unsigned long long u64;

__device__ double g_acc = 0.0;
__device__ unsigned int g_done = 0;

// ---- packed f32x2 helpers (sm_103a FFMA2/FADD2/FMUL2 via PTX) ----
__device__ __forceinline__ u64 pk2(float lo, float hi) {
    u64 r; asm("mov.b64 %0, {%1, %2};" : "=l"(r) : "f"(lo), "f"(hi)); return r;
}
__device__ __forceinline__ void upk2(u64 p, float& lo, float& hi) {
    asm("mov.b64 {%0, %1}, %2;" : "=f"(lo), "=f"(hi) : "l"(p));
}
__device__ __forceinline__ u64 add2_(u64 a, u64 b) {
    u64 r; asm("add.rn.f32x2 %0, %1, %2;" : "=l"(r) : "l"(a), "l"(b)); return r;
}
__device__ __forceinline__ u64 mul2_(u64 a, u64 b) {
    u64 r; asm("mul.rn.f32x2 %0, %1, %2;" : "=l"(r) : "l"(a), "l"(b)); return r;
}
__device__ __forceinline__ u64 fma2_(u64 a, u64 b, u64 c) {
    u64 r; asm("fma.rn.f32x2 %0, %1, %2, %3;" : "=l"(r) : "l"(a), "l"(b), "l"(c));
    return r;
}

// Per-plane stats for this thread's element pair, packed:
//   gx = sum_dy [v(x+1)-v(x-1)], gy = rowsum(y+1)-rowsum(y-1), b = 3x3 box
// Shuffle/edge path scalar; h packed per row; b/gy assembled packed.
__device__ __forceinline__ void rows_stats_p(
    const float2* __restrict__ v, const float* __restrict__ e, int lane,
    u64 NEG1, u64& gx, u64& gy, u64& b)
{
    u64 hp[3];
    float d0s = 0.0f, d1s = 0.0f;
#pragma unroll
    for (int r = 0; r < 3; ++r) {
        float l  = __shfl_up_sync(FULLMASK, v[r].y, 1);
        float rr = __shfl_down_sync(FULLMASK, v[r].x, 1);
        if (lane == 0)  l  = e[r];
        if (lane == 31) rr = e[r];
        float s = v[r].x + v[r].y;
        hp[r] = pk2(l + s, s + rr);          // (h0, h1)
        if (r == 0) { d0s = v[r].y - l; d1s = rr - v[r].x; }
        else        { d0s += v[r].y - l; d1s += rr - v[r].x; }
    }
    gx = pk2(d0s, d1s);
    gy = fma2_(hp[0], NEG1, hp[2]);          // h[2] - h[0]
    b  = add2_(add2_(hp[0], hp[1]), hp[2]);
}

// One z-step. Slot `o` = stats(z-1), `m` = stats(z). Loads batched up front;
// combine fully packed. Pointers pI/pJ/mp pre-advanced per step (no z clamp
// here; the single clamped step is handled by the caller's pointer adjust).
#define STEP(o, m)                                                            \
    {                                                                         \
        float2 vI[3], vJ[3];                                                  \
        float  eI[3], eJ[3];                                                  \
        _Pragma("unroll")                                                     \
        for (int r = 0; r < 3; ++r)                                           \
            vI[r] = *reinterpret_cast<const float2*>(pI + co[r]);             \
        _Pragma("unroll")                                                     \
        for (int r = 0; r < 3; ++r)                                           \
            vJ[r] = *reinterpret_cast<const float2*>(pJ + co[r]);             \
        float2 m2 = *reinterpret_cast<const float2*>(mp);                     \
        if (edge) {                                                           \
            _Pragma("unroll")                                                 \
            for (int r = 0; r < 3; ++r) {                                     \
                eI[r] = pI[co[r] + dxe];                                      \
                eJ[r] = pJ[co[r] + dxe];                                      \
            }                                                                 \
        }                                                                     \
        u64 nxI, nyI, nbI, nxJ, nyJ, nbJ;                                     \
        rows_stats_p(vI, eI, lane, NEG1, nxI, nyI, nbI);                      \
        rows_stats_p(vJ, eJ, lane, NEG1, nxJ, nyJ, nbJ);                      \
        u64 Ix = add2_(add2_(gxI[o], gxI[m]), nxI);                           \
        u64 Iy = add2_(add2_(gyI[o], gyI[m]), nyI);                           \
        u64 Iz = fma2_(bI[o], NEG1, nbI);                                     \
        u64 Jx = add2_(add2_(gxJ[o], gxJ[m]), nxJ);                           \
        u64 Jy = add2_(add2_(gyJ[o], gyJ[m]), nyJ);                           \
        u64 Jz = fma2_(bJ[o], NEG1, nbJ);                                     \
        u64 ssi  = fma2_(Ix, Ix, fma2_(Iy, Iy, mul2_(Iz, Iz)));               \
        u64 ssj  = fma2_(Jx, Jx, fma2_(Jy, Jy, mul2_(Jz, Jz)));               \
        u64 sdot = fma2_(Ix, Jx, fma2_(Iy, Jy, mul2_(Iz, Jz)));               \
        u64 num = mul2_(sdot, sdot);                                          \
        u64 den = mul2_(add2_(ssi, EPS2), add2_(ssj, EPS2));                  \
        float n0, n1, de0, de1;                                               \
        upk2(num, n0, n1);                                                    \
        upk2(den, de0, de1);                                                  \
        float ngf0 = __fdividef(n0, de0);                                     \
        float ngf1 = __fdividef(n1, de1);                                     \
        acc0 = fmaf(1.0f - ngf0, m2.x, acc0);                                 \
        acc1 = fmaf(1.0f - ngf1, m2.y, acc1);                                 \
        gxI[o] = nxI; gyI[o] = nyI; bI[o] = nbI;                              \
        gxJ[o] = nxJ; gyJ[o] = nyJ; bJ[o] = nbJ;                              \
        pI += NXY; pJ += NXY; mp += NXY;                                      \
    }

__global__ __launch_bounds__(NTHREADS, 6)
void ngf_kernel(const float* __restrict__ I,
                const float* __restrict__ J,
                const float* __restrict__ M,
                float* __restrict__ out)
{
    __shared__ float warp_sums[WYD];

    const int lane = threadIdx.x;
    const int wy   = threadIdx.y;
    const int tid  = wy * 32 + lane;
    const int seg  = blockIdx.x;
    const int x2   = seg * SEGW + lane * VEC;
    const int y    = blockIdx.y * WYD + wy;
    const int z0   = blockIdx.z * ZCHUNK;

    const u64 NEG1 = pk2(-1.0f, -1.0f);
    const u64 EPS2 = pk2(0.04f, 0.04f);   // folded scale: ngf = sdot^2/((ssi+.04)(ssj+.04))

    const bool edge = (lane == 0) || (lane == 31);
    // Edge-lane neighbor offset relative to this thread's float2 base:
    //   lane 0 : left neighbor p[-1], or p[0] (=v.x, clamp) at x2==0
    //   lane 31: right neighbor p[2], or p[1] (=v.y, clamp) at x2+2==NX
    int dxe = 0;
    if (lane == 0)  dxe = (x2 > 0) ? -1 : 0;
    if (lane == 31) dxe = (x2 + VEC < NX) ? 2 : 1;

    // Clamped (y-row*NX + x2) offsets, constant across z
    int co[3];
#pragma unroll
    for (int r = 0; r < 3; ++r) {
        int gy = y - 1 + r;
        gy = gy < 0 ? 0 : (gy > NY - 1 ? NY - 1 : gy);
        co[r] = gy * NX + x2;
    }

    // 2-slot rolling z-state, packed element pairs
    u64 gxI[2], gyI[2], bI[2];
    u64 gxJ[2], gyJ[2], bJ[2];

    // Prologue: plane z0-1 (clamped) -> slot 0, plane z0 -> slot 1
    {
        int gzm = z0 - 1 < 0 ? 0 : z0 - 1;
#pragma unroll
        for (int s = 0; s < 2; ++s) {
            size_t zoff = (size_t)(s == 0 ? gzm : z0) * NXY;
            const float* qI = I + zoff;
            const float* qJ = J + zoff;
            float2 vI[3], vJ[3];
            float  eI[3], eJ[3];
#pragma unroll
            for (int r = 0; r < 3; ++r) {
                vI[r] = *reinterpret_cast<const float2*>(qI + co[r]);
                vJ[r] = *reinterpret_cast<const float2*>(qJ + co[r]);
            }
            if (edge) {
#pragma unroll
                for (int r = 0; r < 3; ++r) {
                    eI[r] = qI[co[r] + dxe];
                    eJ[r] = qJ[co[r] + dxe];
                }
            }
            rows_stats_p(vI, eI, lane, NEG1, gxI[s], gyI[s], bI[s]);
            rows_stats_p(vJ, eJ, lane, NEG1, gxJ[s], gyJ[s], bJ[s]);
        }
    }

    float acc0 = 0.0f, acc1 = 0.0f;

    // Streaming pointers: STEP k loads plane z0+k+1; bumped by NXY per step.
    const float* pI = I + (size_t)(z0 + 1) * NXY + 0;
    const float* pJ = J + (size_t)(z0 + 1) * NXY + 0;
    const float* mp = M + (size_t)z0 * NXY + co[1];   // co[1] == y*NX + x2

    // Only the very last step of the last z-block reads plane NZ -> clamp it
    // by pointing that step back at plane NZ-1.
    const long lastAdj = (z0 + ZCHUNK >= NZ) ? -(long)NXY : 0;

    // First ZCHUNK-4 steps (no clamp possible), then the peeled last group.
    for (int kb = 0; kb < ZCHUNK - 4; kb += 4) {
        STEP(0, 1)
        STEP(1, 0)
        STEP(0, 1)
        STEP(1, 0)
    }
    STEP(0, 1)
    STEP(1, 0)
    STEP(0, 1)
    pI += lastAdj; pJ += lastAdj;
    STEP(1, 0)

    float acc = acc0 + acc1;

    // Block reduction
#pragma unroll
    for (int off = 16; off > 0; off >>= 1)
        acc += __shfl_xor_sync(FULLMASK, acc, off);
    if (lane == 0) warp_sums[wy] = acc;
    __syncthreads();

    if (tid == 0) {
        float v = warp_sums[0] + warp_sums[1] + warp_sums[2] + warp_sums[3];
        atomicAdd(&g_acc, (double)v);
        __threadfence();
        unsigned prev = atomicAdd(&g_done, 1u);
        if (prev == NBLOCKS - 1) {
            // All other blocks' g_acc adds are fenced before their g_done
            // increments, so an atomic read here sees the full sum.
            double tot = atomicAdd(&g_acc, 0.0);
            out[0] = (float)(tot * (1.0 / (double)((long long)NX * NY * NZ)));
            g_acc = 0.0;       // reset for next replay (deterministic)
            __threadfence();
            g_done = 0;
        }
    }
}

extern "C" void kernel_launch(void* const* d_in, const int* in_sizes, int n_in,
                              void* d_out, int out_size) {
    const float* I = (const float*)d_in[0];
    const float* J = (const float*)d_in[1];
    const float* M = (const float*)d_in[2];
    float* out = (float*)d_out;

    dim3 block(32, WYD, 1);
    dim3 grid(GXB, GYB, GZB);   // 3 x 48 x 6 = 864 CTAs
    ngf_kernel<<<grid, block>>>(I, J, M, out);
}

// round 13
// speedup vs baseline: 1.0043x; 1.0043x over previous
#include <cuda_runtime.h>
#include <cuda_bf16.h>

#define NX 192
#define NY 192
#define NZ 192
#define NXY (NX * NY)

#define VEC 2                     // float2 per thread in x
#define SEGW (32 * VEC)           // 64 x per CTA (and per warp)
#define WARPS 8                   // 8 warps/CTA, 1 output row each
#define NTHREADS (32 * WARPS)     // 256
#define ROWS_SM (WARPS + 2)       // 10 smem rows: yb-1 .. yb+8
#define ZCHUNK 32
#define GXB (NX / SEGW)           // 3
#define GYB (NY / WARPS)          // 24
#define GZB (NZ / ZCHUNK)         // 6
#define NBLOCKS (GXB * GYB * GZB) // 432 (single wave at 3 CTAs/SM)

#define FULLMASK 0xFFFFFFFFu

__device__ double g_acc = 0.0;
__device__ unsigned int g_done = 0;

// One row of one image: h (x 3-box) and d (x central diff) for this thread's
// element pair. Returns (h0, h1, d0, d1).
__device__ __forceinline__ float4 row_hd(const float* __restrict__ p, int co,
                                         int lane, int dxe)
{
    float2 v = *reinterpret_cast<const float2*>(p + co);
    float l  = __shfl_up_sync(FULLMASK, v.y, 1);
    float rr = __shfl_down_sync(FULLMASK, v.x, 1);
    if ((lane == 0) | (lane == 31)) {
        float e = p[co + dxe];        // clamp: dxe==0/1 folds back onto v
        if (lane == 0) l = e; else rr = e;
    }
    float s = v.x + v.y;
    return make_float4(l + s, s + rr, v.y - l, rr - v.x);
}

// One z-round using smem buffer `o` (== state slot written). DO_COMBINE=1:
// also emit output plane (slots o=z-1, m=z, fresh=z+1) and advance mask ptr.
#define ZROUND(o, m, DO_COMBINE)                                              \
    {                                                                         \
        float4 hIm = row_hd(pI, co_main, lane, dxe);                          \
        float4 hJm = row_hd(pJ, co_main, lane, dxe);                          \
        hd[o][0][smrow_main][lane] = hIm;                                     \
        hd[o][1][smrow_main][lane] = hJm;                                     \
        if (hasHalo) {                                                        \
            hd[o][0][smrow_halo][lane] = row_hd(pI, co_halo, lane, dxe);      \
            hd[o][1][smrow_halo][lane] = row_hd(pJ, co_halo, lane, dxe);      \
        }                                                                     \
        float2 m2 = make_float2(0.f, 0.f);                                    \
        if (DO_COMBINE) m2 = *reinterpret_cast<const float2*>(mp);            \
        __syncthreads();                                                      \
        float4 rI0 = hd[o][0][w][lane], rI2 = hd[o][0][w + 2][lane];          \
        float4 rJ0 = hd[o][1][w][lane], rJ2 = hd[o][1][w + 2][lane];          \
        float nxI0 = rI0.z + hIm.z + rI2.z, nxI1 = rI0.w + hIm.w + rI2.w;     \
        float nyI0 = rI2.x - rI0.x,         nyI1 = rI2.y - rI0.y;             \
        float nbI0 = rI0.x + hIm.x + rI2.x, nbI1 = rI0.y + hIm.y + rI2.y;     \
        float nxJ0 = rJ0.z + hJm.z + rJ2.z, nxJ1 = rJ0.w + hJm.w + rJ2.w;     \
        float nyJ0 = rJ2.x - rJ0.x,         nyJ1 = rJ2.y - rJ0.y;             \
        float nbJ0 = rJ0.x + hJm.x + rJ2.x, nbJ1 = rJ0.y + hJm.y + rJ2.y;     \
        if (DO_COMBINE) {                                                     \
            {                                                                 \
                float Ix = gxI[o][0] + gxI[m][0] + nxI0;                      \
                float Iy = gyI[o][0] + gyI[m][0] + nyI0;                      \
                float Iz = nbI0 - bI[o][0];                                   \
                float Jx = gxJ[o][0] + gxJ[m][0] + nxJ0;                      \
                float Jy = gyJ[o][0] + gyJ[m][0] + nyJ0;                      \
                float Jz = nbJ0 - bJ[o][0];                                   \
                float ssi  = fmaf(Ix, Ix, fmaf(Iy, Iy, Iz * Iz));             \
                float ssj  = fmaf(Jx, Jx, fmaf(Jy, Jy, Jz * Jz));             \
                float sdot = fmaf(Ix, Jx, fmaf(Iy, Jy, Iz * Jz));             \
                float ngf  = __fdividef(sdot * sdot,                          \
                                        (ssi + 0.04f) * (ssj + 0.04f));       \
                acc0 = fmaf(1.0f - ngf, m2.x, acc0);                          \
            }                                                                 \
            {                                                                 \
                float Ix = gxI[o][1] + gxI[m][1] + nxI1;                      \
                float Iy = gyI[o][1] + gyI[m][1] + nyI1;                      \
                float Iz = nbI1 - bI[o][1];                                   \
                float Jx = gxJ[o][1] + gxJ[m][1] + nxJ1;                      \
                float Jy = gyJ[o][1] + gyJ[m][1] + nyJ1;                      \
                float Jz = nbJ1 - bJ[o][1];                                   \
                float ssi  = fmaf(Ix, Ix, fmaf(Iy, Iy, Iz * Iz));             \
                float ssj  = fmaf(Jx, Jx, fmaf(Jy, Jy, Jz * Jz));             \
                float sdot = fmaf(Ix, Jx, fmaf(Iy, Jy, Iz * Jz));             \
                float ngf  = __fdividef(sdot * sdot,                          \
                                        (ssi + 0.04f) * (ssj + 0.04f));       \
                acc1 = fmaf(1.0f - ngf, m2.y, acc1);                          \
            }                                                                 \
            mp += NXY;                                                        \
        }                                                                     \
        gxI[o][0] = nxI0; gxI[o][1] = nxI1;                                   \
        gyI[o][0] = nyI0; gyI[o][1] = nyI1;                                   \
        bI[o][0]  = nbI0; bI[o][1]  = nbI1;                                   \
        gxJ[o][0] = nxJ0; gxJ[o][1] = nxJ1;                                   \
        gyJ[o][0] = nyJ0; gyJ[o][1] = nyJ1;                                   \
        bJ[o][0]  = nbJ0; bJ[o][1]  = nbJ1;                                   \
        pI += NXY; pJ += NXY;                                                 \
    }

__global__ __launch_bounds__(NTHREADS, 3)
void ngf_kernel(const float* __restrict__ I,
                const float* __restrict__ J,
                const float* __restrict__ M,
                float* __restrict__ out)
{
    // [buf][img][row][lane] : (h0, h1, d0, d1) per lane element-pair
    __shared__ float4 hd[2][2][ROWS_SM][32];
    __shared__ float warp_sums[WARPS];

    const int lane = threadIdx.x;
    const int w    = threadIdx.y;          // warp id == output row in CTA
    const int tid  = w * 32 + lane;
    const int seg  = blockIdx.x;
    const int x2   = seg * SEGW + lane * VEC;
    const int yb   = blockIdx.y * WARPS;
    const int z0   = blockIdx.z * ZCHUNK;

    // Edge-lane neighbor offset relative to the float2 base (0/1 = clamp)
    int dxe = 0;
    if (lane == 0)  dxe = (x2 > 0) ? -1 : 0;
    if (lane == 31) dxe = (x2 + VEC < NX) ? 2 : 1;

    // Row assignments: smem rows 0..9 <-> global rows yb-1 .. yb+8.
    // Warp w computes smem row w+1 (its own output row). Warps 0,1 also
    // compute the halo rows (0 and 9), y-clamped.
    const int smrow_main = w + 1;
    const int gy_main    = yb + w;                       // always in [0,191]
    const int co_main    = gy_main * NX + x2;
    const bool hasHalo   = (w < 2);
    int smrow_halo = 0, co_halo = 0;
    if (w == 0) {
        smrow_halo = 0;
        int gy = yb - 1 < 0 ? 0 : yb - 1;
        co_halo = gy * NX + x2;
    } else if (w == 1) {
        smrow_halo = ROWS_SM - 1;
        int gy = yb + WARPS > NY - 1 ? NY - 1 : yb + WARPS;
        co_halo = gy * NX + x2;
    }

    // 2-slot rolling z-state (slot = smem buf parity)
    float gxI[2][VEC], gyI[2][VEC], bI[2][VEC];
    float gxJ[2][VEC], gyJ[2][VEC], bJ[2][VEC];

    float acc0 = 0.0f, acc1 = 0.0f;

    const float* pI;
    const float* pJ;
    const float* mp = M + (size_t)z0 * NXY + co_main;

    // Prologue round A: plane clamp(z0-1) -> buf/slot 0 (no combine)
    {
        int gzm = z0 - 1 < 0 ? 0 : z0 - 1;
        pI = I + (size_t)gzm * NXY;
        pJ = J + (size_t)gzm * NXY;
        ZROUND(0, 1, 0)
    }
    // Prologue round B: plane z0 -> buf/slot 1 (no combine)
    pI = I + (size_t)z0 * NXY;
    pJ = J + (size_t)z0 * NXY;
    ZROUND(1, 0, 0)
    // pI/pJ now point at plane z0+1 == the plane step 0 must process.

    // Only the final step of the last z-block would read plane NZ; clamp it.
    const long lastAdj = (z0 + ZCHUNK >= NZ) ? -(long)NXY : 0;

    // Steps 0..ZCHUNK-3 (step k: buf/slot o = k&1)
    for (int kb = 0; kb < ZCHUNK - 2; kb += 2) {
        ZROUND(0, 1, 1)
        ZROUND(1, 0, 1)
    }
    ZROUND(0, 1, 1)
    pI += lastAdj; pJ += lastAdj;
    ZROUND(1, 0, 1)

    float acc = acc0 + acc1;

    // Block reduction (8 warps)
#pragma unroll
    for (int off = 16; off > 0; off >>= 1)
        acc += __shfl_xor_sync(FULLMASK, acc, off);
    if (lane == 0) warp_sums[w] = acc;
    __syncthreads();

    if (tid == 0) {
        float v = 0.0f;
#pragma unroll
        for (int i = 0; i < WARPS; ++i) v += warp_sums[i];
        atomicAdd(&g_acc, (double)v);
        __threadfence();
        unsigned prev = atomicAdd(&g_done, 1u);
        if (prev == NBLOCKS - 1) {
            // All other blocks' g_acc adds are fenced before their g_done
            // increments, so an atomic read here sees the full sum.
            double tot = atomicAdd(&g_acc, 0.0);
            out[0] = (float)(tot * (1.0 / (double)((long long)NX * NY * NZ)));
            g_acc = 0.0;       // reset for next replay (deterministic)
            __threadfence();
            g_done = 0;
        }
    }
}

extern "C" void kernel_launch(void* const* d_in, const int* in_sizes, int n_in,
                              void* d_out, int out_size) {
    const float* I = (const float*)d_in[0];
    const float* J = (const float*)d_in[1];
    const float* M = (const float*)d_in[2];
    float* out = (float*)d_out;

    dim3 block(32, WARPS, 1);
    dim3 grid(GXB, GYB, GZB);   // 3 x 24 x 6 = 432 CTAs
    ngf_kernel<<<grid, block>>>(I, J, M, out);
}

// round 14
// speedup vs baseline: 1.2523x; 1.2469x over previous
#include <cuda_runtime.h>
#include <cuda_bf16.h>

#define NX 192
#define NY 192
#define NZ 192
#define NXY (NX * NY)

#define VEC 2                    // float2 per thread in x
#define SEGW (32 * VEC)          // 64 x per warp
#define WYD 4                    // 4 warps/CTA, 1 y-row each
#define NTHREADS 128
#define GXB (NX / SEGW)          // 3
#define GYB (NY / WYD)           // 48
#define GZB 5                    // uneven z-chunks: 38,38,38,38,40
#define NBLOCKS (GXB * GYB * GZB) // 720 (single wave at 5 CTAs/SM)

#define FULLMASK 0xFFFFFFFFu

__device__ double g_acc = 0.0;
__device__ unsigned int g_done = 0;

// From preloaded row float2 v[3] (+ edge scalars e[3] for lanes 0/31),
// compute this thread's 2-element plane stats:
//   gx = sum_dy [v(x+1)-v(x-1)], gy = rowsum(y+1)-rowsum(y-1), b = 3x3 box
__device__ __forceinline__ void rows_stats(
    const float2* __restrict__ v, const float* __restrict__ e, int lane,
    float& gx0, float& gx1, float& gy0, float& gy1, float& b0, float& b1)
{
    float h0[3], h1[3], d0s = 0.f, d1s = 0.f;
#pragma unroll
    for (int r = 0; r < 3; ++r) {
        float l  = __shfl_up_sync(FULLMASK, v[r].y, 1);
        float rr = __shfl_down_sync(FULLMASK, v[r].x, 1);
        if (lane == 0)  l  = e[r];
        if (lane == 31) rr = e[r];
        float s = v[r].x + v[r].y;
        h0[r] = l + s;
        h1[r] = s + rr;
        d0s += v[r].y - l;
        d1s += rr - v[r].x;
    }
    gx0 = d0s;
    gx1 = d1s;
    gy0 = h0[2] - h0[0];
    gy1 = h1[2] - h1[0];
    b0  = h0[0] + h0[1] + h0[2];
    b1  = h1[0] + h1[1] + h1[2];
}

// Load one plane's rows (+ edge scalars) from pI/pJ into buffer BUF, then
// advance the plane pointers. Pure load issue — no consumption.
#define PREFETCH(BUF)                                                         \
    {                                                                         \
        _Pragma("unroll")                                                     \
        for (int r = 0; r < 3; ++r)                                           \
            vI##BUF[r] = *reinterpret_cast<const float2*>(pI + co[r]);        \
        _Pragma("unroll")                                                     \
        for (int r = 0; r < 3; ++r)                                           \
            vJ##BUF[r] = *reinterpret_cast<const float2*>(pJ + co[r]);        \
        if (edge) {                                                           \
            _Pragma("unroll")                                                 \
            for (int r = 0; r < 3; ++r) {                                     \
                eI##BUF[r] = pI[co[r] + dxe];                                 \
                eJ##BUF[r] = pJ[co[r] + dxe];                                 \
            }                                                                 \
        }                                                                     \
        pI += NXY; pJ += NXY;                                                 \
    }

// Compute plane stats from buffer BUF into temporaries n*.
#define STATS(BUF)                                                            \
    rows_stats(vI##BUF, eI##BUF, lane, ngxI0, ngxI1, ngyI0, ngyI1, nbI0, nbI1);\
    rows_stats(vJ##BUF, eJ##BUF, lane, ngxJ0, ngxJ1, ngyJ0, ngyJ1, nbJ0, nbJ1);

// Combine + state overwrite for slot pair (o = z-1, m = z), mask advance.
#define COMBINE(o, m)                                                         \
    {                                                                         \
        float2 m2 = *reinterpret_cast<const float2*>(mp);                     \
        {                                                                     \
            float Ix = gxI[o][0] + gxI[m][0] + ngxI0;                         \
            float Iy = gyI[o][0] + gyI[m][0] + ngyI0;                         \
            float Iz = nbI0 - bI[o][0];                                       \
            float Jx = gxJ[o][0] + gxJ[m][0] + ngxJ0;                         \
            float Jy = gyJ[o][0] + gyJ[m][0] + ngyJ0;                         \
            float Jz = nbJ0 - bJ[o][0];                                       \
            float ssi  = fmaf(Ix, Ix, fmaf(Iy, Iy, Iz * Iz));                 \
            float ssj  = fmaf(Jx, Jx, fmaf(Jy, Jy, Jz * Jz));                 \
            float sdot = fmaf(Ix, Jx, fmaf(Iy, Jy, Iz * Jz));                 \
            float ngf  = __fdividef(sdot * sdot,                              \
                                    (ssi + 0.04f) * (ssj + 0.04f));           \
            acc0 = fmaf(1.0f - ngf, m2.x, acc0);                              \
        }                                                                     \
        {                                                                     \
            float Ix = gxI[o][1] + gxI[m][1] + ngxI1;                         \
            float Iy = gyI[o][1] + gyI[m][1] + ngyI1;                         \
            float Iz = nbI1 - bI[o][1];                                       \
            float Jx = gxJ[o][1] + gxJ[m][1] + ngxJ1;                         \
            float Jy = gyJ[o][1] + gyJ[m][1] + ngyJ1;                         \
            float Jz = nbJ1 - bJ[o][1];                                       \
            float ssi  = fmaf(Ix, Ix, fmaf(Iy, Iy, Iz * Iz));                 \
            float ssj  = fmaf(Jx, Jx, fmaf(Jy, Jy, Jz * Jz));                 \
            float sdot = fmaf(Ix, Jx, fmaf(Iy, Jy, Iz * Jz));                 \
            float ngf  = __fdividef(sdot * sdot,                              \
                                    (ssi + 0.04f) * (ssj + 0.04f));           \
            acc1 = fmaf(1.0f - ngf, m2.y, acc1);                              \
        }                                                                     \
        gxI[o][0] = ngxI0; gxI[o][1] = ngxI1;                                 \
        gyI[o][0] = ngyI0; gyI[o][1] = ngyI1;                                 \
        bI[o][0]  = nbI0;  bI[o][1]  = nbI1;                                  \
        gxJ[o][0] = ngxJ0; gxJ[o][1] = ngxJ1;                                 \
        gyJ[o][0] = ngyJ0; gyJ[o][1] = ngyJ1;                                 \
        bJ[o][0]  = nbJ0;  bJ[o][1]  = nbJ1;                                  \
        mp += NXY;                                                            \
    }

// Full pipelined step: issue next plane's loads into NXT, then consume CUR.
#define STEP_PF(o, m, CUR, NXT)                                               \
    {                                                                         \
        PREFETCH(NXT)                                                         \
        float ngxI0, ngxI1, ngyI0, ngyI1, nbI0, nbI1;                         \
        float ngxJ0, ngxJ1, ngyJ0, ngyJ1, nbJ0, nbJ1;                         \
        STATS(CUR)                                                            \
        COMBINE(o, m)                                                         \
    }

// Final step: consume CUR, no prefetch.
#define STEP_LAST(o, m, CUR)                                                  \
    {                                                                         \
        float ngxI0, ngxI1, ngyI0, ngyI1, nbI0, nbI1;                         \
        float ngxJ0, ngxJ1, ngyJ0, ngyJ1, nbJ0, nbJ1;                         \
        STATS(CUR)                                                            \
        COMBINE(o, m)                                                         \
    }

__global__ __launch_bounds__(NTHREADS, 5)
void ngf_kernel(const float* __restrict__ I,
                const float* __restrict__ J,
                const float* __restrict__ M,
                float* __restrict__ out)
{
    __shared__ float warp_sums[WYD];

    const int lane = threadIdx.x;
    const int wy   = threadIdx.y;
    const int tid  = wy * 32 + lane;
    const int seg  = blockIdx.x;
    const int x2   = seg * SEGW + lane * VEC;
    const int y    = blockIdx.y * WYD + wy;
    const int z0   = blockIdx.z * 38;
    const int zlen = (blockIdx.z == GZB - 1) ? 40 : 38;   // 4*38 + 40 = 192

    const bool edge = (lane == 0) || (lane == 31);
    // Edge-lane neighbor offset relative to the float2 base (clamp folds to 0/1)
    int dxe = 0;
    if (lane == 0)  dxe = (x2 > 0) ? -1 : 0;
    if (lane == 31) dxe = (x2 + VEC < NX) ? 2 : 1;

    // Clamped (y-row*NX + x2) offsets, constant across z
    int co[3];
#pragma unroll
    for (int r = 0; r < 3; ++r) {
        int gy = y - 1 + r;
        gy = gy < 0 ? 0 : (gy > NY - 1 ? NY - 1 : gy);
        co[r] = gy * NX + x2;
    }

    // Double-buffered plane rows (+ edge patches)
    float2 vIA[3], vJA[3], vIB[3], vJB[3];
    float  eIA[3], eJA[3], eIB[3], eJB[3];

    // 2-slot rolling z-state
    float gxI[2][VEC], gyI[2][VEC], bI[2][VEC];
    float gxJ[2][VEC], gyJ[2][VEC], bJ[2][VEC];

    float acc0 = 0.0f, acc1 = 0.0f;

    // Streaming plane pointers
    const float* pI;
    const float* pJ;
    const float* mp = M + (size_t)z0 * NXY + co[1];  // co[1] == y*NX + x2

    // Prologue: stats for clamp(z0-1) -> slot 0 and z0 -> slot 1
    {
        int gzm = z0 - 1 < 0 ? 0 : z0 - 1;
        pI = I + (size_t)gzm * NXY;
        pJ = J + (size_t)gzm * NXY;
        PREFETCH(A)                                   // plane gzm, bump
        if (z0 == 0) { pI -= NXY; pJ -= NXY; }        // re-read plane 0
        {
            float ngxI0, ngxI1, ngyI0, ngyI1, nbI0, nbI1;
            float ngxJ0, ngxJ1, ngyJ0, ngyJ1, nbJ0, nbJ1;
            STATS(A)
            gxI[0][0] = ngxI0; gxI[0][1] = ngxI1;
            gyI[0][0] = ngyI0; gyI[0][1] = ngyI1;
            bI[0][0]  = nbI0;  bI[0][1]  = nbI1;
            gxJ[0][0] = ngxJ0; gxJ[0][1] = ngxJ1;
            gyJ[0][0] = ngyJ0; gyJ[0][1] = ngyJ1;
            bJ[0][0]  = nbJ0;  bJ[0][1]  = nbJ1;
        }
        PREFETCH(B)                                   // plane z0, bump to z0+1
        {
            float ngxI0, ngxI1, ngyI0, ngyI1, nbI0, nbI1;
            float ngxJ0, ngxJ1, ngyJ0, ngyJ1, nbJ0, nbJ1;
            STATS(B)
            gxI[1][0] = ngxI0; gxI[1][1] = ngxI1;
            gyI[1][0] = ngyI0; gyI[1][1] = ngyI1;
            bI[1][0]  = nbI0;  bI[1][1]  = nbI1;
            gxJ[1][0] = ngxJ0; gxJ[1][1] = ngxJ1;
            gyJ[1][0] = ngyJ0; gyJ[1][1] = ngyJ1;
            bJ[1][0]  = nbJ0;  bJ[1][1]  = nbJ1;
        }
        PREFETCH(A)                                   // plane z0+1 (step 0's data)
    }

    // Steps 0 .. zlen-3 (even count), fully pipelined
    for (int k = 0; k < zlen - 2; k += 2) {
        STEP_PF(0, 1, A, B)
        STEP_PF(1, 0, B, A)
    }

    // Step zlen-2: its prefetch targets plane z0+zlen; clamp for last block.
    if (z0 + zlen >= NZ) { pI -= NXY; pJ -= NXY; }
    STEP_PF(0, 1, A, B)
    // Step zlen-1: consume B, no prefetch.
    STEP_LAST(1, 0, B)

    float acc = acc0 + acc1;

    // Block reduction
#pragma unroll
    for (int off = 16; off > 0; off >>= 1)
        acc += __shfl_xor_sync(FULLMASK, acc, off);
    if (lane == 0) warp_sums[wy] = acc;
    __syncthreads();

    if (tid == 0) {
        float v = warp_sums[0] + warp_sums[1] + warp_sums[2] + warp_sums[3];
        atomicAdd(&g_acc, (double)v);
        __threadfence();
        unsigned prev = atomicAdd(&g_done, 1u);
        if (prev == NBLOCKS - 1) {
            // All other blocks' g_acc adds are fenced before their g_done
            // increments, so an atomic read here sees the full sum.
            double tot = atomicAdd(&g_acc, 0.0);
            out[0] = (float)(tot * (1.0 / (double)((long long)NX * NY * NZ)));
            g_acc = 0.0;       // reset for next replay (deterministic)
            __threadfence();
            g_done = 0;
        }
    }
}

extern "C" void kernel_launch(void* const* d_in, const int* in_sizes, int n_in,
                              void* d_out, int out_size) {
    const float* I = (const float*)d_in[0];
    const float* J = (const float*)d_in[1];
    const float* M = (const float*)d_in[2];
    float* out = (float*)d_out;

    dim3 block(32, WYD, 1);
    dim3 grid(GXB, GYB, GZB);   // 3 x 48 x 5 = 720 CTAs
    ngf_kernel<<<grid, block>>>(I, J, M, out);
}